// round 9
// baseline (speedup 1.0000x reference)
#include <cuda_runtime.h>
#include <cstdint>

#define BB 64
#define PP 256
#define NN 1000
typedef unsigned long long ull;

__device__ float g_K[BB * NN * 128];
__device__ float g_V[BB * NN * 128];
__device__ float g_Q[BB * PP * 128];

// ---- f32x2 / memory helpers ----
__device__ __forceinline__ ull ffma2(ull a, ull b, ull c) {
    ull d; asm("fma.rn.f32x2 %0,%1,%2,%3;" : "=l"(d) : "l"(a), "l"(b), "l"(c)); return d;
}
__device__ __forceinline__ ull fmul2(ull a, ull b) {
    ull d; asm("mul.rn.f32x2 %0,%1,%2;" : "=l"(d) : "l"(a), "l"(b)); return d;
}
__device__ __forceinline__ ull pack2(float lo, float hi) {
    ull d; asm("mov.b64 %0,{%1,%2};" : "=l"(d) : "f"(lo), "f"(hi)); return d;
}
__device__ __forceinline__ float hadd2(ull a) {
    float lo, hi; asm("mov.b64 {%0,%1},%2;" : "=f"(lo), "=f"(hi) : "l"(a)); return lo + hi;
}
__device__ __forceinline__ void lds2x64(const float* p, ull& a, ull& b) {
    uint32_t ad = (uint32_t)__cvta_generic_to_shared(p);
    asm("ld.shared.v2.b64 {%0,%1},[%2];" : "=l"(a), "=l"(b) : "r"(ad));
}
__device__ __forceinline__ ull lds64(const float* p) {
    uint32_t ad = (uint32_t)__cvta_generic_to_shared(p);
    ull a; asm("ld.shared.b64 %0,[%1];" : "=l"(a) : "r"(ad)); return a;
}
__device__ __forceinline__ void sts64(float* p, ull v) {
    uint32_t ad = (uint32_t)__cvta_generic_to_shared(p);
    asm volatile("st.shared.b64 [%0],%1;" :: "r"(ad), "l"(v));
}
__device__ __forceinline__ void sts128z(float* p) {
    uint32_t ad = (uint32_t)__cvta_generic_to_shared(p);
    asm volatile("st.shared.v4.b32 [%0],{%1,%1,%1,%1};" :: "r"(ad), "r"(0));
}
__device__ __forceinline__ void sts32(float* p, float v) {
    uint32_t ad = (uint32_t)__cvta_generic_to_shared(p);
    asm volatile("st.shared.b32 [%0],%1;" :: "r"(ad), "f"(v));
}
__device__ __forceinline__ void ldg2x64(const float* p, ull& a, ull& b) {
    asm("ld.global.nc.v2.b64 {%0,%1},[%2];" : "=l"(a), "=l"(b) : "l"(p));
}
__device__ __forceinline__ void cp16(float* dst, const float* src) {
    uint32_t d = (uint32_t)__cvta_generic_to_shared(dst);
    asm volatile("cp.async.cg.shared.global [%0],[%1],16;" :: "r"(d), "l"(src));
}
__device__ __forceinline__ void cp4(float* dst, const float* src) {
    uint32_t d = (uint32_t)__cvta_generic_to_shared(dst);
    asm volatile("cp.async.ca.shared.global [%0],[%1],4;" :: "r"(d), "l"(src));
}
__device__ __forceinline__ void cp_commit() { asm volatile("cp.async.commit_group;"); }
template <int N> __device__ __forceinline__ void cp_wait() {
    asm volatile("cp.async.wait_group %0;" :: "n"(N));
}

// ---------------------------------------------------------------------------
// K/V projection (unchanged; measured ~119us). 32 rows/block, 256 threads.
// ---------------------------------------------------------------------------
__global__ __launch_bounds__(256) void kv_proj(const float* __restrict__ enc,
                                               const float* __restrict__ Wk,
                                               const float* __restrict__ Wv) {
    __shared__ float xs[32 * 128];
    int t = threadIdx.x;
    int row0 = blockIdx.x * 32;
    const float4* src = (const float4*)(enc + (size_t)row0 * 128);
    float4* xs4 = (float4*)xs;
#pragma unroll
    for (int i = t; i < 1024; i += 256) xs4[i] = src[i];
    __syncthreads();

    int mat = t >> 7, rh = (t >> 6) & 1, cp = t & 63;
    const float* W = mat ? Wv : Wk;
    float* out = mat ? g_V : g_K;
    const float* xb = xs + rh * 2048;

    ull acc[32];
#pragma unroll
    for (int i = 0; i < 32; i++) acc[i] = 0ull;

#pragma unroll 2
    for (int k = 0; k < 128; k += 2) {
        ull w0 = pack2(W[k * 128 + cp], W[(k + 1) * 128 + cp]);
        ull w1 = pack2(W[k * 128 + cp + 64], W[(k + 1) * 128 + cp + 64]);
#pragma unroll
        for (int r = 0; r < 16; r++) {
            ull x = lds64(xb + r * 128 + k);
            acc[r]      = ffma2(x, w0, acc[r]);
            acc[16 + r] = ffma2(x, w1, acc[16 + r]);
        }
    }
#pragma unroll
    for (int r = 0; r < 16; r++) {
        size_t row = (size_t)(row0 + rh * 16 + r) * 128;
        out[row + cp]      = hadd2(acc[r]);
        out[row + cp + 64] = hadd2(acc[16 + r]);
    }
}

// ---------------------------------------------------------------------------
// Q projection (unchanged)
// ---------------------------------------------------------------------------
__global__ __launch_bounds__(256) void q_proj(const float* __restrict__ last,
                                              const float* __restrict__ attr,
                                              const float* __restrict__ Wq) {
    __shared__ float xs[16 * 132];
    int row0 = blockIdx.x * 16;
    int t = threadIdx.x;
#pragma unroll
    for (int i = t; i < 2048; i += 256) {
        int r = i >> 7, c = i & 127;
        xs[r * 132 + c] = last[(size_t)(row0 + r) * 128 + c];
    }
    if (t < 16) xs[t * 132 + 128] = attr[row0 + t];
    __syncthreads();

    int rh = t >> 7, col = t & 127;
    const float* xr = xs + rh * 8 * 132;
    float acc[8] = {0, 0, 0, 0, 0, 0, 0, 0};
#pragma unroll 4
    for (int in = 0; in < 129; in++) {
        float w = Wq[in * 128 + col];
#pragma unroll
        for (int r = 0; r < 8; r++) acc[r] += xr[r * 132 + in] * w;
    }
#pragma unroll
    for (int r = 0; r < 8; r++)
        g_Q[(size_t)(row0 + rh * 8 + r) * 128 + col] = acc[r];
}

// ---------------------------------------------------------------------------
// Fused attention: 32-query tiles, 512 blocks, 3 CTAs/SM target.
// warp = head h, lane = query. smem 54272 B:
//   om   [0, 4224)      out -> mh, stride 132
//   inv  [4224, 4288)
//   work [4288, 13568)  9280 floats:
//     A: k0 2048 | k1 2048 | v0 2048 | v1 2048 | m0 544 | m1 544  (16-key chunks)
//     Wo half: 8192
//     B: enc 64x132 = 8448 (single buffer)
// ---------------------------------------------------------------------------
__global__ __launch_bounds__(256, 3) void attn_kernel(
        const float* __restrict__ enc, const float* __restrict__ mask,
        const float* __restrict__ Wo, const float* __restrict__ bo,
        float* __restrict__ probs) {
    extern __shared__ float sm[];
    float* om    = sm;
    float* inv_s = sm + 4224;
    float* work  = sm + 4288;

    int t = threadIdx.x;
    int b = blockIdx.x >> 3;
    int p0 = (blockIdx.x & 7) * 32;
    int h = t >> 5, lane = t & 31;

    const float* Kb = g_K + (size_t)b * NN * 128;
    const float* Vb = g_V + (size_t)b * NN * 128;
    const float* Mb = mask + (size_t)(b * PP + p0) * NN;

    const int NCH = 63;  // ceil(1000/16)

    auto stageA = [&](int chunk) {
        int buf = chunk & 1;
        int base = chunk * 16;
        int nv = NN - base; if (nv > 16) nv = 16;
        float* kd = work + buf * 2048;
        float* vd = work + 4096 + buf * 2048;
        float* md = work + 8192 + buf * 544;
#pragma unroll
        for (int j = 0; j < 2; j++) {
            int i = t + j * 256;
            int n = i >> 5, seg = i & 31;
            if (n < nv) {
                cp16(kd + n * 128 + seg * 4, Kb + (size_t)(base + n) * 128 + seg * 4);
                cp16(vd + n * 128 + seg * 4, Vb + (size_t)(base + n) * 128 + seg * 4);
            } else {
                sts128z(kd + n * 128 + seg * 4);
                sts128z(vd + n * 128 + seg * 4);
            }
        }
#pragma unroll
        for (int j = 0; j < 2; j++) {
            int i = t + j * 256;
            int p = i >> 4, n = i & 15;
            if (n < nv) cp4(md + p * 17 + n, Mb + (size_t)p * NN + base + n);
            else        sts32(md + p * 17 + n, -1e30f);
        }
    };

    // q (0.25 prescaled)
    ull qpk[8];
    {
        const float* qp = g_Q + (size_t)(b * PP + p0 + lane) * 128 + h * 16;
        ull c = pack2(0.25f, 0.25f);
#pragma unroll
        for (int j = 0; j < 4; j++) {
            ull a0, a1;
            ldg2x64(qp + 4 * j, a0, a1);
            qpk[2 * j]     = fmul2(a0, c);
            qpk[2 * j + 1] = fmul2(a1, c);
        }
    }

    float l = 0.f;
    ull acc[8];
#pragma unroll
    for (int j = 0; j < 8; j++) acc[j] = 0ull;

    stageA(0); cp_commit();
    stageA(1); cp_commit();

    // ---- phase A: 63 chunks of 16 keys, double-buffered ----
    for (int c = 0; c < NCH; c++) {
        if (c == NCH - 1) cp_wait<0>(); else cp_wait<1>();
        __syncthreads();

        int buf = c & 1;
        const float* k_s = work + buf * 2048;
        const float* v_s = work + 4096 + buf * 2048;
        const float* mA  = work + 8192 + buf * 544 + lane * 17;

#pragma unroll 4
        for (int n = 0; n < 16; n++) {
            const float* kp = k_s + n * 128 + h * 16;
            ull k0, k1, k2, k3, k4, k5, k6, k7;
            lds2x64(kp,      k0, k1);
            lds2x64(kp + 4,  k2, k3);
            lds2x64(kp + 8,  k4, k5);
            lds2x64(kp + 12, k6, k7);
            ull d = fmul2(qpk[0], k0);
            d = ffma2(qpk[1], k1, d); d = ffma2(qpk[2], k2, d);
            d = ffma2(qpk[3], k3, d); d = ffma2(qpk[4], k4, d);
            d = ffma2(qpk[5], k5, d); d = ffma2(qpk[6], k6, d);
            d = ffma2(qpk[7], k7, d);
            float w = __expf(hadd2(d) + mA[n]);
            l += w;
            const float* vp = v_s + n * 128 + h * 16;
            ull v0, v1, v2, v3, v4, v5, v6, v7;
            lds2x64(vp,      v0, v1);
            lds2x64(vp + 4,  v2, v3);
            lds2x64(vp + 8,  v4, v5);
            lds2x64(vp + 12, v6, v7);
            ull ww = pack2(w, w);
            acc[0] = ffma2(ww, v0, acc[0]); acc[1] = ffma2(ww, v1, acc[1]);
            acc[2] = ffma2(ww, v2, acc[2]); acc[3] = ffma2(ww, v3, acc[3]);
            acc[4] = ffma2(ww, v4, acc[4]); acc[5] = ffma2(ww, v5, acc[5]);
            acc[6] = ffma2(ww, v6, acc[6]); acc[7] = ffma2(ww, v7, acc[7]);
        }
        __syncthreads();
        if (c + 2 < NCH) { stageA(c + 2); cp_commit(); }
    }

    // finalize: om[lane][h*16..] = acc / l
    {
        float inv = 1.f / l;
        ull iv = pack2(inv, inv);
        float* op = om + lane * 132 + h * 16;
#pragma unroll
        for (int j = 0; j < 8; j++) sts64(op + 2 * j, fmul2(acc[j], iv));
    }

    // ---- Wo GEMM in two staged halves; thread = (p = t>>3, 16 e's) ----
    {
        int p = t >> 3;
        int eg = (t & 7) * 16;
        ull a[8];
        {
            ull b0, b1, b2, b3, b4, b5, b6, b7;
            ldg2x64(bo + eg,      b0, b1);
            ldg2x64(bo + eg + 4,  b2, b3);
            ldg2x64(bo + eg + 8,  b4, b5);
            ldg2x64(bo + eg + 12, b6, b7);
            a[0] = b0; a[1] = b1; a[2] = b2; a[3] = b3;
            a[4] = b4; a[5] = b5; a[6] = b6; a[7] = b7;
        }
#pragma unroll
        for (int half = 0; half < 2; half++) {
            __syncthreads();   // prior readers of work done (also publishes om)
#pragma unroll
            for (int j = 0; j < 8; j++) {
                int i = t + j * 256;
                cp16(work + i * 4, Wo + half * 8192 + i * 4);
            }
            cp_commit(); cp_wait<0>();
            __syncthreads();
            const float* xrow = om + p * 132 + half * 64;
#pragma unroll 4
            for (int kl = 0; kl < 64; kl++) {
                float x = xrow[kl];
                ull xx = pack2(x, x);
                const float* wp = work + kl * 128 + eg;
                ull w0, w1, w2, w3, w4, w5, w6, w7;
                lds2x64(wp,      w0, w1);
                lds2x64(wp + 4,  w2, w3);
                lds2x64(wp + 8,  w4, w5);
                lds2x64(wp + 12, w6, w7);
                a[0] = ffma2(xx, w0, a[0]); a[1] = ffma2(xx, w1, a[1]);
                a[2] = ffma2(xx, w2, a[2]); a[3] = ffma2(xx, w3, a[3]);
                a[4] = ffma2(xx, w4, a[4]); a[5] = ffma2(xx, w5, a[5]);
                a[6] = ffma2(xx, w6, a[6]); a[7] = ffma2(xx, w7, a[7]);
            }
        }
        __syncthreads();   // all om reads done before in-place overwrite
        float* mp = om + p * 132 + eg;
#pragma unroll
        for (int j = 0; j < 8; j++) sts64(mp + 2 * j, a[j]);
    }
    __syncthreads();

    // ---- phase B: 16 chunks of 64 nodes, single buffer; thread = 4p x 2n ----
    int pq = t >> 5, nh = t & 31;
    float rs[4] = {0.f, 0.f, 0.f, 0.f};
    float* pout = probs + (size_t)(b * PP + p0) * NN;
    const float inv_se = 0.08838834764831845f;
    const float* Eb = enc + (size_t)b * NN * 128;
    const float* mrow = om + (4 * pq) * 132;

    for (int c = 0; c < 16; c++) {
        int base = c * 64;
        int nv = NN - base; if (nv > 64) nv = 64;
        // stage (single buffer; barrier above/below isolates from compute)
#pragma unroll
        for (int j = 0; j < 8; j++) {
            int i = t + j * 256;
            int n = i >> 5, seg = i & 31;
            if (n < nv)
                cp16(work + n * 132 + seg * 4, Eb + (size_t)(base + n) * 128 + seg * 4);
        }
        cp_commit(); cp_wait<0>();
        __syncthreads();

        const float* e0p = work + nh * 132;
        const float* e1p = work + (nh + 32) * 132;
        ull a[4][2];
#pragma unroll
        for (int pp = 0; pp < 4; pp++) { a[pp][0] = 0ull; a[pp][1] = 0ull; }

#pragma unroll 4
        for (int k = 0; k < 128; k += 4) {
            ull e00, e01, e10, e11;
            lds2x64(e0p + k, e00, e01);
            lds2x64(e1p + k, e10, e11);
#pragma unroll
            for (int pp = 0; pp < 4; pp++) {
                ull m0, m1;
                lds2x64(mrow + pp * 132 + k, m0, m1);
                a[pp][0] = ffma2(m0, e00, a[pp][0]);
                a[pp][0] = ffma2(m1, e01, a[pp][0]);
                a[pp][1] = ffma2(m0, e10, a[pp][1]);
                a[pp][1] = ffma2(m1, e11, a[pp][1]);
            }
        }
#pragma unroll
        for (int j = 0; j < 2; j++) {
            int n = nh + 32 * j;
            if (n < nv) {
#pragma unroll
                for (int pp = 0; pp < 4; pp++) {
                    int p = 4 * pq + pp;
                    float sd = hadd2(a[pp][j]);
                    float x = sd * inv_se;
                    x = fminf(fmaxf(x, -30.f), 30.f);
                    float ex = __expf(-2.f * x);
                    float th = __fdividef(1.f - ex, 1.f + ex);
                    float lg = 10.f * th + Mb[(size_t)p * NN + base + n];
                    float w = __expf(lg - 10.f);
                    rs[pp] += w;
                    pout[(size_t)p * NN + base + n] = w;
                }
            }
        }
        __syncthreads();   // compute reads done before next restage
    }

    // row sums -> inverse, then normalize in-place
#pragma unroll
    for (int off = 16; off; off >>= 1) {
#pragma unroll
        for (int pp = 0; pp < 4; pp++)
            rs[pp] += __shfl_xor_sync(0xFFFFFFFFu, rs[pp], off);
    }
    if (nh == 0) {
#pragma unroll
        for (int pp = 0; pp < 4; pp++) inv_s[4 * pq + pp] = 1.f / rs[pp];
    }
    __syncthreads();
#pragma unroll
    for (int p = 0; p < 32; p++) {
        float ivp = inv_s[p];
        for (int i = t; i < NN; i += 256)
            pout[(size_t)p * NN + i] *= ivp;
    }
}

// ---------------------------------------------------------------------------
extern "C" void kernel_launch(void* const* d_in, const int* in_sizes, int n_in,
                              void* d_out, int out_size) {
    const float* enc  = (const float*)d_in[0];
    const float* last = (const float*)d_in[1];
    const float* attr = (const float*)d_in[2];
    const float* mask = (const float*)d_in[3];
    const float* Wq   = (const float*)d_in[4];
    const float* Wk   = (const float*)d_in[5];
    const float* Wv   = (const float*)d_in[6];
    const float* Wo   = (const float*)d_in[7];
    const float* bo   = (const float*)d_in[8];
    float* out = (float*)d_out;

    cudaFuncSetAttribute(attn_kernel,
                         cudaFuncAttributeMaxDynamicSharedMemorySize, 54272);

    kv_proj<<<2000, 256>>>(enc, Wk, Wv);
    q_proj<<<1024, 256>>>(last, attr, Wq);
    attn_kernel<<<512, 256, 54272>>>(enc, mask, Wo, bo, out);
}

// round 10
// speedup vs baseline: 1.1303x; 1.1303x over previous
#include <cuda_runtime.h>
#include <cstdint>

#define BB 64
#define PP 256
#define NN 1000
typedef unsigned long long ull;

__device__ float g_K[BB * NN * 128];
__device__ float g_V[BB * NN * 128];
__device__ float g_Q[BB * PP * 128];

// ---- f32x2 / memory helpers ----
__device__ __forceinline__ ull ffma2(ull a, ull b, ull c) {
    ull d; asm("fma.rn.f32x2 %0,%1,%2,%3;" : "=l"(d) : "l"(a), "l"(b), "l"(c)); return d;
}
__device__ __forceinline__ ull fmul2(ull a, ull b) {
    ull d; asm("mul.rn.f32x2 %0,%1,%2;" : "=l"(d) : "l"(a), "l"(b)); return d;
}
__device__ __forceinline__ ull pack2(float lo, float hi) {
    ull d; asm("mov.b64 %0,{%1,%2};" : "=l"(d) : "f"(lo), "f"(hi)); return d;
}
__device__ __forceinline__ float hadd2(ull a) {
    float lo, hi; asm("mov.b64 {%0,%1},%2;" : "=f"(lo), "=f"(hi) : "l"(a)); return lo + hi;
}
__device__ __forceinline__ void lds2x64(const float* p, ull& a, ull& b) {
    uint32_t ad = (uint32_t)__cvta_generic_to_shared(p);
    asm("ld.shared.v2.b64 {%0,%1},[%2];" : "=l"(a), "=l"(b) : "r"(ad));
}
__device__ __forceinline__ ull lds64(const float* p) {
    uint32_t ad = (uint32_t)__cvta_generic_to_shared(p);
    ull a; asm("ld.shared.b64 %0,[%1];" : "=l"(a) : "r"(ad)); return a;
}
__device__ __forceinline__ void sts64(float* p, ull v) {
    uint32_t ad = (uint32_t)__cvta_generic_to_shared(p);
    asm volatile("st.shared.b64 [%0],%1;" :: "r"(ad), "l"(v));
}
__device__ __forceinline__ void sts128z(float* p) {
    uint32_t ad = (uint32_t)__cvta_generic_to_shared(p);
    asm volatile("st.shared.v4.b32 [%0],{%1,%1,%1,%1};" :: "r"(ad), "r"(0));
}
__device__ __forceinline__ void sts32(float* p, float v) {
    uint32_t ad = (uint32_t)__cvta_generic_to_shared(p);
    asm volatile("st.shared.b32 [%0],%1;" :: "r"(ad), "f"(v));
}
__device__ __forceinline__ void ldg2x64(const float* p, ull& a, ull& b) {
    asm("ld.global.nc.v2.b64 {%0,%1},[%2];" : "=l"(a), "=l"(b) : "l"(p));
}
__device__ __forceinline__ void cp16(float* dst, const float* src) {
    uint32_t d = (uint32_t)__cvta_generic_to_shared(dst);
    asm volatile("cp.async.cg.shared.global [%0],[%1],16;" :: "r"(d), "l"(src));
}
__device__ __forceinline__ void cp4(float* dst, const float* src) {
    uint32_t d = (uint32_t)__cvta_generic_to_shared(dst);
    asm volatile("cp.async.ca.shared.global [%0],[%1],4;" :: "r"(d), "l"(src));
}
__device__ __forceinline__ void cp_commit() { asm volatile("cp.async.commit_group;"); }
template <int N> __device__ __forceinline__ void cp_wait() {
    asm volatile("cp.async.wait_group %0;" :: "n"(N));
}

// ---------------------------------------------------------------------------
// Fused K/V + Q projection. Blocks [0,2000): K/V (32 rows each);
// blocks [2000,3024): Q (16 rows each).
// ---------------------------------------------------------------------------
__global__ __launch_bounds__(256) void proj_kernel(
        const float* __restrict__ enc, const float* __restrict__ Wk,
        const float* __restrict__ Wv, const float* __restrict__ last,
        const float* __restrict__ attr, const float* __restrict__ Wq) {
    __shared__ float xs[32 * 128];
    int t = threadIdx.x;

    if (blockIdx.x < 2000) {
        // ---- K/V projection (proven form) ----
        int row0 = blockIdx.x * 32;
        const float4* src = (const float4*)(enc + (size_t)row0 * 128);
        float4* xs4 = (float4*)xs;
#pragma unroll
        for (int i = t; i < 1024; i += 256) xs4[i] = src[i];
        __syncthreads();

        int mat = t >> 7, rh = (t >> 6) & 1, cp = t & 63;
        const float* W = mat ? Wv : Wk;
        float* out = mat ? g_V : g_K;
        const float* xb = xs + rh * 2048;

        ull acc[32];
#pragma unroll
        for (int i = 0; i < 32; i++) acc[i] = 0ull;

#pragma unroll 2
        for (int k = 0; k < 128; k += 2) {
            ull w0 = pack2(W[k * 128 + cp], W[(k + 1) * 128 + cp]);
            ull w1 = pack2(W[k * 128 + cp + 64], W[(k + 1) * 128 + cp + 64]);
#pragma unroll
            for (int r = 0; r < 16; r++) {
                ull x = lds64(xb + r * 128 + k);
                acc[r]      = ffma2(x, w0, acc[r]);
                acc[16 + r] = ffma2(x, w1, acc[16 + r]);
            }
        }
#pragma unroll
        for (int r = 0; r < 16; r++) {
            size_t row = (size_t)(row0 + rh * 16 + r) * 128;
            out[row + cp]      = hadd2(acc[r]);
            out[row + cp + 64] = hadd2(acc[16 + r]);
        }
    } else {
        // ---- Q projection: 16 rows ----
        int row0 = (blockIdx.x - 2000) * 16;
#pragma unroll
        for (int i = t; i < 2048; i += 256) {
            int r = i >> 7, c = i & 127;
            xs[r * 132 + c] = last[(size_t)(row0 + r) * 128 + c];
        }
        if (t < 16) xs[t * 132 + 128] = attr[row0 + t];
        __syncthreads();

        int rh = t >> 7, col = t & 127;
        const float* xr = xs + rh * 8 * 132;
        float acc[8] = {0, 0, 0, 0, 0, 0, 0, 0};
#pragma unroll 4
        for (int in = 0; in < 129; in++) {
            float w = Wq[in * 128 + col];
#pragma unroll
            for (int r = 0; r < 8; r++) acc[r] += xr[r * 132 + in] * w;
        }
#pragma unroll
        for (int r = 0; r < 8; r++)
            g_Q[(size_t)(row0 + rh * 8 + r) * 128 + col] = acc[r];
    }
}

// ---------------------------------------------------------------------------
// Fused attention (R7 base): 32-query tiles, 512 blocks, 256 threads.
// warp = head h, lane = query. Inner loop batched in groups of 4 n:
// 4 independent score chains + 4 exps, then 4 V accumulations.
// smem floats: mh 4224 | inv 32 | out 4224 | work 19008  = 27488 (109952 B)
// ---------------------------------------------------------------------------
__global__ __launch_bounds__(256, 2) void attn_kernel(
        const float* __restrict__ enc, const float* __restrict__ mask,
        const float* __restrict__ Wo, const float* __restrict__ bo,
        float* __restrict__ probs) {
    extern __shared__ float sm[];
    float* mh_s  = sm;
    float* inv_s = sm + 4224;
    float* out_s = sm + 4256;
    float* work  = sm + 8480;

    int t = threadIdx.x;
    int b = blockIdx.x >> 3;
    int p0 = (blockIdx.x & 7) * 32;
    int h = t >> 5, lane = t & 31;

    const float* Kb = g_K + (size_t)b * NN * 128;
    const float* Vb = g_V + (size_t)b * NN * 128;
    const float* Mb = mask + (size_t)(b * PP + p0) * NN;

    auto stageA = [&](int chunk) {
        int buf = chunk & 1;
        int base = chunk * 32;
        int nv = NN - base; if (nv > 32) nv = 32;
        float* kd = work + buf * 4224;
        float* vd = work + 8448 + buf * 4224;
        float* md = work + 16896 + buf * 1056;
#pragma unroll
        for (int j = 0; j < 4; j++) {
            int i = t + j * 256;
            int n = i >> 5, seg = i & 31;
            if (n < nv) {
                cp16(kd + n * 132 + seg * 4, Kb + (size_t)(base + n) * 128 + seg * 4);
                cp16(vd + n * 132 + seg * 4, Vb + (size_t)(base + n) * 128 + seg * 4);
            } else {
                sts128z(kd + n * 132 + seg * 4);
                sts128z(vd + n * 132 + seg * 4);
            }
        }
#pragma unroll
        for (int j = 0; j < 4; j++) {
            int i = t + j * 256;
            int p = i >> 5, n = i & 31;
            if (n < nv) cp4(md + p * 33 + n, Mb + (size_t)p * NN + base + n);
            else        sts32(md + p * 33 + n, -1e30f);
        }
    };
    auto stageB = [&](int chunk) {
        int buf = chunk & 1;
        int base = chunk * 64;
        int nv = NN - base; if (nv > 64) nv = 64;
        float* ed = work + buf * 8448;
        const float* Eb = enc + (size_t)b * NN * 128;
#pragma unroll
        for (int j = 0; j < 8; j++) {
            int i = t + j * 256;
            int n = i >> 5, seg = i & 31;
            if (n < nv)
                cp16(ed + n * 132 + seg * 4, Eb + (size_t)(base + n) * 128 + seg * 4);
        }
    };

    // q (0.25 prescaled)
    ull qpk[8];
    {
        const float* qp = g_Q + (size_t)(b * PP + p0 + lane) * 128 + h * 16;
        ull c = pack2(0.25f, 0.25f);
#pragma unroll
        for (int j = 0; j < 4; j++) {
            ull a0, a1;
            ldg2x64(qp + 4 * j, a0, a1);
            qpk[2 * j]     = fmul2(a0, c);
            qpk[2 * j + 1] = fmul2(a1, c);
        }
    }

    float l = 0.f;
    ull acc[8];
#pragma unroll
    for (int j = 0; j < 8; j++) acc[j] = 0ull;

    stageA(0); cp_commit();
    stageA(1); cp_commit();

    // ---- phase A: 32 chunks of 32 keys, n batched 4-wide ----
    for (int c = 0; c < 32; c++) {
        if (c == 31) cp_wait<0>(); else cp_wait<1>();
        __syncthreads();

        int buf = c & 1;
        const float* k_s = work + buf * 4224;
        const float* v_s = work + 8448 + buf * 4224;
        const float* mA  = work + 16896 + buf * 1056 + lane * 33;

#pragma unroll
        for (int g = 0; g < 8; g++) {
            float w4[4];
            // 4 independent score chains
#pragma unroll
            for (int i = 0; i < 4; i++) {
                int n = 4 * g + i;
                const float* kp = k_s + n * 132 + h * 16;
                ull k0, k1, k2, k3, k4, k5, k6, k7;
                lds2x64(kp,      k0, k1);
                lds2x64(kp + 4,  k2, k3);
                lds2x64(kp + 8,  k4, k5);
                lds2x64(kp + 12, k6, k7);
                ull d = fmul2(qpk[0], k0);
                d = ffma2(qpk[1], k1, d); d = ffma2(qpk[2], k2, d);
                d = ffma2(qpk[3], k3, d); d = ffma2(qpk[4], k4, d);
                d = ffma2(qpk[5], k5, d); d = ffma2(qpk[6], k6, d);
                d = ffma2(qpk[7], k7, d);
                w4[i] = __expf(hadd2(d) + mA[n]);
            }
            l += (w4[0] + w4[1]) + (w4[2] + w4[3]);
            // 4 V accumulations
#pragma unroll
            for (int i = 0; i < 4; i++) {
                int n = 4 * g + i;
                const float* vp = v_s + n * 132 + h * 16;
                ull v0, v1, v2, v3, v4, v5, v6, v7;
                lds2x64(vp,      v0, v1);
                lds2x64(vp + 4,  v2, v3);
                lds2x64(vp + 8,  v4, v5);
                lds2x64(vp + 12, v6, v7);
                ull ww = pack2(w4[i], w4[i]);
                acc[0] = ffma2(ww, v0, acc[0]); acc[1] = ffma2(ww, v1, acc[1]);
                acc[2] = ffma2(ww, v2, acc[2]); acc[3] = ffma2(ww, v3, acc[3]);
                acc[4] = ffma2(ww, v4, acc[4]); acc[5] = ffma2(ww, v5, acc[5]);
                acc[6] = ffma2(ww, v6, acc[6]); acc[7] = ffma2(ww, v7, acc[7]);
            }
        }
        __syncthreads();
        if (c + 2 < 32) { stageA(c + 2); cp_commit(); }
    }

    // finalize: out_s[lane][h*16..] = acc / l
    {
        float inv = 1.f / l;
        ull iv = pack2(inv, inv);
        float* op = out_s + lane * 132 + h * 16;
#pragma unroll
        for (int j = 0; j < 8; j++) sts64(op + 2 * j, fmul2(acc[j], iv));
    }
    __syncthreads();

    // stage Wo (64KB) into work
    {
        const float4* Wo4 = (const float4*)Wo;
#pragma unroll
        for (int j = 0; j < 16; j++) {
            int i = t + j * 256;
            cp16(work + i * 4, (const float*)(Wo4 + i));
        }
        cp_commit(); cp_wait<0>();
    }
    __syncthreads();

    // mh = out @ Wo + bo  (thread = 2p x 8e; Wo from smem)
    {
        int pg = t >> 4;
        int eg = (t & 15) * 8;
        const float* Wos = work;
        ull a0[4], a1[4];
        {
            ull b0, b1, b2, b3;
            ldg2x64(bo + eg, b0, b1);
            ldg2x64(bo + eg + 4, b2, b3);
            a0[0] = b0; a0[1] = b1; a0[2] = b2; a0[3] = b3;
            a1[0] = b0; a1[1] = b1; a1[2] = b2; a1[3] = b3;
        }
        const float* x0p = out_s + (2 * pg) * 132;
        const float* x1p = x0p + 132;
#pragma unroll 4
        for (int k = 0; k < 128; k++) {
            float x0 = x0p[k], x1 = x1p[k];
            ull xx0 = pack2(x0, x0), xx1 = pack2(x1, x1);
            const float* wp = Wos + k * 128 + eg;
            ull w0, w1, w2, w3;
            lds2x64(wp, w0, w1);
            lds2x64(wp + 4, w2, w3);
            a0[0] = ffma2(xx0, w0, a0[0]); a0[1] = ffma2(xx0, w1, a0[1]);
            a0[2] = ffma2(xx0, w2, a0[2]); a0[3] = ffma2(xx0, w3, a0[3]);
            a1[0] = ffma2(xx1, w0, a1[0]); a1[1] = ffma2(xx1, w1, a1[1]);
            a1[2] = ffma2(xx1, w2, a1[2]); a1[3] = ffma2(xx1, w3, a1[3]);
        }
        float* m0 = mh_s + (2 * pg) * 132 + eg;
        float* m1 = m0 + 132;
#pragma unroll
        for (int j = 0; j < 4; j++) { sts64(m0 + 2 * j, a0[j]); sts64(m1 + 2 * j, a1[j]); }
    }
    __syncthreads();   // Wo reads done; work free for enc

    stageB(0); cp_commit();
    stageB(1); cp_commit();

    // ---- phase B: 16 chunks of 64 nodes; thread = 4p x 2n ----
    int pq = t >> 5, nh = t & 31;
    float rs[4] = {0.f, 0.f, 0.f, 0.f};
    float* pout = probs + (size_t)(b * PP + p0) * NN;
    const float inv_se = 0.08838834764831845f;
    const float* mrow = mh_s + (4 * pq) * 132;

    for (int c = 0; c < 16; c++) {
        if (c == 15) cp_wait<0>(); else cp_wait<1>();
        __syncthreads();

        int buf = c & 1;
        int base = c * 64;
        int nv = NN - base; if (nv > 64) nv = 64;
        const float* e_s = work + buf * 8448;
        const float* e0p = e_s + nh * 132;
        const float* e1p = e_s + (nh + 32) * 132;

        ull a[4][2];
#pragma unroll
        for (int pp = 0; pp < 4; pp++) { a[pp][0] = 0ull; a[pp][1] = 0ull; }

#pragma unroll 4
        for (int k = 0; k < 128; k += 4) {
            ull e00, e01, e10, e11;
            lds2x64(e0p + k, e00, e01);
            lds2x64(e1p + k, e10, e11);
#pragma unroll
            for (int pp = 0; pp < 4; pp++) {
                ull m0, m1;
                lds2x64(mrow + pp * 132 + k, m0, m1);
                a[pp][0] = ffma2(m0, e00, a[pp][0]);
                a[pp][0] = ffma2(m1, e01, a[pp][0]);
                a[pp][1] = ffma2(m0, e10, a[pp][1]);
                a[pp][1] = ffma2(m1, e11, a[pp][1]);
            }
        }
#pragma unroll
        for (int j = 0; j < 2; j++) {
            int n = nh + 32 * j;
            if (n < nv) {
#pragma unroll
                for (int pp = 0; pp < 4; pp++) {
                    int p = 4 * pq + pp;
                    float sd = hadd2(a[pp][j]);
                    float x = sd * inv_se;
                    x = fminf(fmaxf(x, -30.f), 30.f);
                    float ex = __expf(-2.f * x);
                    float th = __fdividef(1.f - ex, 1.f + ex);
                    float lg = 10.f * th + Mb[(size_t)p * NN + base + n];
                    float w = __expf(lg - 10.f);
                    rs[pp] += w;
                    pout[(size_t)p * NN + base + n] = w;
                }
            }
        }
        __syncthreads();
        if (c + 2 < 16) { stageB(c + 2); cp_commit(); }
    }

    // row sums -> inverse, then normalize in-place
#pragma unroll
    for (int off = 16; off; off >>= 1) {
#pragma unroll
        for (int pp = 0; pp < 4; pp++)
            rs[pp] += __shfl_xor_sync(0xFFFFFFFFu, rs[pp], off);
    }
    if (nh == 0) {
#pragma unroll
        for (int pp = 0; pp < 4; pp++) inv_s[4 * pq + pp] = 1.f / rs[pp];
    }
    __syncthreads();
#pragma unroll
    for (int p = 0; p < 32; p++) {
        float ivp = inv_s[p];
        for (int i = t; i < NN; i += 256)
            pout[(size_t)p * NN + i] *= ivp;
    }
}

// ---------------------------------------------------------------------------
extern "C" void kernel_launch(void* const* d_in, const int* in_sizes, int n_in,
                              void* d_out, int out_size) {
    const float* enc  = (const float*)d_in[0];
    const float* last = (const float*)d_in[1];
    const float* attr = (const float*)d_in[2];
    const float* mask = (const float*)d_in[3];
    const float* Wq   = (const float*)d_in[4];
    const float* Wk   = (const float*)d_in[5];
    const float* Wv   = (const float*)d_in[6];
    const float* Wo   = (const float*)d_in[7];
    const float* bo   = (const float*)d_in[8];
    float* out = (float*)d_out;

    cudaFuncSetAttribute(attn_kernel,
                         cudaFuncAttributeMaxDynamicSharedMemorySize, 109952);

    proj_kernel<<<3024, 256>>>(enc, Wk, Wv, last, attr, Wq);
    attn_kernel<<<512, 256, 109952>>>(enc, mask, Wo, bo, out);
}

// round 11
// speedup vs baseline: 1.2135x; 1.0736x over previous
#include <cuda_runtime.h>
#include <cstdint>

#define BB 64
#define PP 256
#define NN 1000
typedef unsigned long long ull;

__device__ float g_K[BB * NN * 128];
__device__ float g_V[BB * NN * 128];
__device__ float g_Q[BB * PP * 128];   // after attnA: holds attention output
#define g_MH g_K                       // mh reuses g_K (dead after attnA)

// ---- f32x2 / memory helpers ----
__device__ __forceinline__ ull ffma2(ull a, ull b, ull c) {
    ull d; asm("fma.rn.f32x2 %0,%1,%2,%3;" : "=l"(d) : "l"(a), "l"(b), "l"(c)); return d;
}
__device__ __forceinline__ ull fmul2(ull a, ull b) {
    ull d; asm("mul.rn.f32x2 %0,%1,%2;" : "=l"(d) : "l"(a), "l"(b)); return d;
}
__device__ __forceinline__ ull pack2(float lo, float hi) {
    ull d; asm("mov.b64 %0,{%1,%2};" : "=l"(d) : "f"(lo), "f"(hi)); return d;
}
__device__ __forceinline__ float hadd2(ull a) {
    float lo, hi; asm("mov.b64 {%0,%1},%2;" : "=f"(lo), "=f"(hi) : "l"(a)); return lo + hi;
}
__device__ __forceinline__ void lds2x64(const float* p, ull& a, ull& b) {
    uint32_t ad = (uint32_t)__cvta_generic_to_shared(p);
    asm("ld.shared.v2.b64 {%0,%1},[%2];" : "=l"(a), "=l"(b) : "r"(ad));
}
__device__ __forceinline__ ull lds64(const float* p) {
    uint32_t ad = (uint32_t)__cvta_generic_to_shared(p);
    ull a; asm("ld.shared.b64 %0,[%1];" : "=l"(a) : "r"(ad)); return a;
}
__device__ __forceinline__ void sts64(float* p, ull v) {
    uint32_t ad = (uint32_t)__cvta_generic_to_shared(p);
    asm volatile("st.shared.b64 [%0],%1;" :: "r"(ad), "l"(v));
}
__device__ __forceinline__ void sts128z(float* p) {
    uint32_t ad = (uint32_t)__cvta_generic_to_shared(p);
    asm volatile("st.shared.v4.b32 [%0],{%1,%1,%1,%1};" :: "r"(ad), "r"(0));
}
__device__ __forceinline__ void sts32(float* p, float v) {
    uint32_t ad = (uint32_t)__cvta_generic_to_shared(p);
    asm volatile("st.shared.b32 [%0],%1;" :: "r"(ad), "f"(v));
}
__device__ __forceinline__ void ldg2x64(const float* p, ull& a, ull& b) {
    asm("ld.global.nc.v2.b64 {%0,%1},[%2];" : "=l"(a), "=l"(b) : "l"(p));
}
__device__ __forceinline__ void stg64(float* p, ull v) {
    asm volatile("st.global.b64 [%0],%1;" :: "l"(p), "l"(v));
}
__device__ __forceinline__ void cp16(float* dst, const float* src) {
    uint32_t d = (uint32_t)__cvta_generic_to_shared(dst);
    asm volatile("cp.async.cg.shared.global [%0],[%1],16;" :: "r"(d), "l"(src));
}
__device__ __forceinline__ void cp4(float* dst, const float* src) {
    uint32_t d = (uint32_t)__cvta_generic_to_shared(dst);
    asm volatile("cp.async.ca.shared.global [%0],[%1],4;" :: "r"(d), "l"(src));
}
__device__ __forceinline__ void cp_commit() { asm volatile("cp.async.commit_group;"); }
template <int N> __device__ __forceinline__ void cp_wait() {
    asm volatile("cp.async.wait_group %0;" :: "n"(N));
}

// ---------------------------------------------------------------------------
// Kernel 1: fused K/V + Q projection (unchanged, measured ~124us).
// ---------------------------------------------------------------------------
__global__ __launch_bounds__(256) void proj_kernel(
        const float* __restrict__ enc, const float* __restrict__ Wk,
        const float* __restrict__ Wv, const float* __restrict__ last,
        const float* __restrict__ attr, const float* __restrict__ Wq) {
    __shared__ float xs[32 * 128];
    int t = threadIdx.x;

    if (blockIdx.x < 2000) {
        int row0 = blockIdx.x * 32;
        const float4* src = (const float4*)(enc + (size_t)row0 * 128);
        float4* xs4 = (float4*)xs;
#pragma unroll
        for (int i = t; i < 1024; i += 256) xs4[i] = src[i];
        __syncthreads();

        int mat = t >> 7, rh = (t >> 6) & 1, cp = t & 63;
        const float* W = mat ? Wv : Wk;
        float* out = mat ? g_V : g_K;
        const float* xb = xs + rh * 2048;

        ull acc[32];
#pragma unroll
        for (int i = 0; i < 32; i++) acc[i] = 0ull;

#pragma unroll 2
        for (int k = 0; k < 128; k += 2) {
            ull w0 = pack2(W[k * 128 + cp], W[(k + 1) * 128 + cp]);
            ull w1 = pack2(W[k * 128 + cp + 64], W[(k + 1) * 128 + cp + 64]);
#pragma unroll
            for (int r = 0; r < 16; r++) {
                ull x = lds64(xb + r * 128 + k);
                acc[r]      = ffma2(x, w0, acc[r]);
                acc[16 + r] = ffma2(x, w1, acc[16 + r]);
            }
        }
#pragma unroll
        for (int r = 0; r < 16; r++) {
            size_t row = (size_t)(row0 + rh * 16 + r) * 128;
            out[row + cp]      = hadd2(acc[r]);
            out[row + cp + 64] = hadd2(acc[16 + r]);
        }
    } else {
        int row0 = (blockIdx.x - 2000) * 16;
#pragma unroll
        for (int i = t; i < 2048; i += 256) {
            int r = i >> 7, c = i & 127;
            xs[r * 132 + c] = last[(size_t)(row0 + r) * 128 + c];
        }
        if (t < 16) xs[t * 132 + 128] = attr[row0 + t];
        __syncthreads();

        int rh = t >> 7, col = t & 127;
        const float* xr = xs + rh * 8 * 132;
        float acc[8] = {0, 0, 0, 0, 0, 0, 0, 0};
#pragma unroll 4
        for (int in = 0; in < 129; in++) {
            float w = Wq[in * 128 + col];
#pragma unroll
            for (int r = 0; r < 8; r++) acc[r] += xr[r * 132 + in] * w;
        }
#pragma unroll
        for (int r = 0; r < 8; r++)
            g_Q[(size_t)(row0 + rh * 8 + r) * 128 + col] = acc[r];
    }
}

// ---------------------------------------------------------------------------
// Kernel 2: flash attention only.  32-query tiles, 512 blocks, 3 CTAs/SM.
// warp = head, lane = query. Writes normalized output IN PLACE over g_Q
// (each block reads exactly the q rows it overwrites; reads precede writes).
// smem: k0/k1 4096 | v0/v1 4096 | m0/m1 1056  = 18496 floats (73984 B)
// ---------------------------------------------------------------------------
__global__ __launch_bounds__(256, 3) void attnA_kernel(
        const float* __restrict__ mask) {
    extern __shared__ float work[];
    int t = threadIdx.x;
    int b = blockIdx.x >> 3;
    int p0 = (blockIdx.x & 7) * 32;
    int h = t >> 5, lane = t & 31;

    const float* Kb = g_K + (size_t)b * NN * 128;
    const float* Vb = g_V + (size_t)b * NN * 128;
    const float* Mb = mask + (size_t)(b * PP + p0) * NN;

    auto stageA = [&](int chunk) {
        int buf = chunk & 1;
        int base = chunk * 32;
        int nv = NN - base; if (nv > 32) nv = 32;
        float* kd = work + buf * 4096;
        float* vd = work + 8192 + buf * 4096;
        float* md = work + 16384 + buf * 1056;
#pragma unroll
        for (int j = 0; j < 4; j++) {
            int i = t + j * 256;
            int n = i >> 5, seg = i & 31;
            if (n < nv) {
                cp16(kd + n * 128 + seg * 4, Kb + (size_t)(base + n) * 128 + seg * 4);
                cp16(vd + n * 128 + seg * 4, Vb + (size_t)(base + n) * 128 + seg * 4);
            } else {
                sts128z(kd + n * 128 + seg * 4);
                sts128z(vd + n * 128 + seg * 4);
            }
        }
#pragma unroll
        for (int j = 0; j < 4; j++) {
            int i = t + j * 256;
            int p = i >> 5, n = i & 31;
            if (n < nv) cp4(md + p * 33 + n, Mb + (size_t)p * NN + base + n);
            else        sts32(md + p * 33 + n, -1e30f);
        }
    };

    // q (0.25 prescaled); g_Q read happens before any write (barrier-ordered)
    ull qpk[8];
    {
        const float* qp = g_Q + (size_t)(b * PP + p0 + lane) * 128 + h * 16;
        ull c = pack2(0.25f, 0.25f);
#pragma unroll
        for (int j = 0; j < 4; j++) {
            ull a0, a1;
            ldg2x64(qp + 4 * j, a0, a1);
            qpk[2 * j]     = fmul2(a0, c);
            qpk[2 * j + 1] = fmul2(a1, c);
        }
    }

    float l = 0.f;
    ull acc[8];
#pragma unroll
    for (int j = 0; j < 8; j++) acc[j] = 0ull;

    stageA(0); cp_commit();
    stageA(1); cp_commit();

    for (int c = 0; c < 32; c++) {
        if (c == 31) cp_wait<0>(); else cp_wait<1>();
        __syncthreads();

        int buf = c & 1;
        const float* k_s = work + buf * 4096;
        const float* v_s = work + 8192 + buf * 4096;
        const float* mA  = work + 16384 + buf * 1056 + lane * 33;

#pragma unroll 4
        for (int n = 0; n < 32; n++) {
            const float* kp = k_s + n * 128 + h * 16;
            ull k0, k1, k2, k3, k4, k5, k6, k7;
            lds2x64(kp,      k0, k1);
            lds2x64(kp + 4,  k2, k3);
            lds2x64(kp + 8,  k4, k5);
            lds2x64(kp + 12, k6, k7);
            ull d = fmul2(qpk[0], k0);
            d = ffma2(qpk[1], k1, d); d = ffma2(qpk[2], k2, d);
            d = ffma2(qpk[3], k3, d); d = ffma2(qpk[4], k4, d);
            d = ffma2(qpk[5], k5, d); d = ffma2(qpk[6], k6, d);
            d = ffma2(qpk[7], k7, d);
            float w = __expf(hadd2(d) + mA[n]);
            l += w;
            const float* vp = v_s + n * 128 + h * 16;
            ull v0, v1, v2, v3, v4, v5, v6, v7;
            lds2x64(vp,      v0, v1);
            lds2x64(vp + 4,  v2, v3);
            lds2x64(vp + 8,  v4, v5);
            lds2x64(vp + 12, v6, v7);
            ull ww = pack2(w, w);
            acc[0] = ffma2(ww, v0, acc[0]); acc[1] = ffma2(ww, v1, acc[1]);
            acc[2] = ffma2(ww, v2, acc[2]); acc[3] = ffma2(ww, v3, acc[3]);
            acc[4] = ffma2(ww, v4, acc[4]); acc[5] = ffma2(ww, v5, acc[5]);
            acc[6] = ffma2(ww, v6, acc[6]); acc[7] = ffma2(ww, v7, acc[7]);
        }
        __syncthreads();
        if (c + 2 < 32) { stageA(c + 2); cp_commit(); }
    }

    // write normalized output over g_Q (this block's own rows)
    {
        float inv = 1.f / l;
        ull iv = pack2(inv, inv);
        float* op = g_Q + (size_t)(b * PP + p0 + lane) * 128 + h * 16;
#pragma unroll
        for (int j = 0; j < 8; j++) stg64(op + 2 * j, fmul2(acc[j], iv));
    }
}

// ---------------------------------------------------------------------------
// Kernel 3: mh = out @ Wo + bo  (kv_proj-shaped GEMM). 512 blocks x 32 rows.
// thread = (row-group t>>6 -> 8 rows, col-pair t&63 -> cols cp, cp+64)
// ---------------------------------------------------------------------------
__global__ __launch_bounds__(256) void mh_proj(const float* __restrict__ Wo,
                                               const float* __restrict__ bo) {
    __shared__ float xs[32 * 128];
    int t = threadIdx.x;
    int row0 = blockIdx.x * 32;
    const float4* src = (const float4*)(g_Q + (size_t)row0 * 128);
    float4* xs4 = (float4*)xs;
#pragma unroll
    for (int i = t; i < 1024; i += 256) xs4[i] = src[i];
    __syncthreads();

    int rg = t >> 6, cp = t & 63;
    const float* xb = xs + rg * 8 * 128;

    ull acc[16];
#pragma unroll
    for (int i = 0; i < 16; i++) acc[i] = 0ull;

#pragma unroll 2
    for (int k = 0; k < 128; k += 2) {
        ull w0 = pack2(Wo[k * 128 + cp], Wo[(k + 1) * 128 + cp]);
        ull w1 = pack2(Wo[k * 128 + cp + 64], Wo[(k + 1) * 128 + cp + 64]);
#pragma unroll
        for (int r = 0; r < 8; r++) {
            ull x = lds64(xb + r * 128 + k);
            acc[r]     = ffma2(x, w0, acc[r]);
            acc[8 + r] = ffma2(x, w1, acc[8 + r]);
        }
    }
    float b0 = bo[cp], b1 = bo[cp + 64];
#pragma unroll
    for (int r = 0; r < 8; r++) {
        size_t row = (size_t)(row0 + rg * 8 + r) * 128;
        g_MH[row + cp]      = hadd2(acc[r]) + b0;
        g_MH[row + cp + 64] = hadd2(acc[8 + r]) + b1;
    }
}

// ---------------------------------------------------------------------------
// Kernel 4: tanh-clipped scoring + final softmax. 512 blocks, 4 CTAs/SM.
// smem: mh 4224 | inv 32 | enc 8448  = 12704 floats (50816 B)
// thread = (warp -> 4 p, lane -> 2 n), 16 chunks of 64 nodes, single buffer.
// ---------------------------------------------------------------------------
__global__ __launch_bounds__(256, 4) void phaseB_kernel(
        const float* __restrict__ enc, const float* __restrict__ mask,
        float* __restrict__ probs) {
    extern __shared__ float sm[];
    float* mh_s  = sm;
    float* inv_s = sm + 4224;
    float* work  = sm + 4256;

    int t = threadIdx.x;
    int b = blockIdx.x >> 3;
    int p0 = (blockIdx.x & 7) * 32;
    int pq = t >> 5, nh = t & 31;

    const float* Mb = mask + (size_t)(b * PP + p0) * NN;
    const float* Eb = enc + (size_t)b * NN * 128;
    float* pout = probs + (size_t)(b * PP + p0) * NN;

    // stage mh tile (32 x 128 -> stride 132)
#pragma unroll
    for (int j = 0; j < 4; j++) {
        int i = t + j * 256;
        int row = i >> 5, seg = i & 31;
        cp16(mh_s + row * 132 + seg * 4,
             g_MH + (size_t)(b * PP + p0 + row) * 128 + seg * 4);
    }
    cp_commit();

    float rs[4] = {0.f, 0.f, 0.f, 0.f};
    const float inv_se = 0.08838834764831845f;
    const float* mrow = mh_s + (4 * pq) * 132;

    for (int c = 0; c < 16; c++) {
        int base = c * 64;
        int nv = NN - base; if (nv > 64) nv = 64;
#pragma unroll
        for (int j = 0; j < 8; j++) {
            int i = t + j * 256;
            int n = i >> 5, seg = i & 31;
            if (n < nv)
                cp16(work + n * 132 + seg * 4, Eb + (size_t)(base + n) * 128 + seg * 4);
        }
        cp_commit(); cp_wait<0>();
        __syncthreads();

        const float* e0p = work + nh * 132;
        const float* e1p = work + (nh + 32) * 132;
        ull a[4][2];
#pragma unroll
        for (int pp = 0; pp < 4; pp++) { a[pp][0] = 0ull; a[pp][1] = 0ull; }

#pragma unroll 4
        for (int k = 0; k < 128; k += 4) {
            ull e00, e01, e10, e11;
            lds2x64(e0p + k, e00, e01);
            lds2x64(e1p + k, e10, e11);
#pragma unroll
            for (int pp = 0; pp < 4; pp++) {
                ull m0, m1;
                lds2x64(mrow + pp * 132 + k, m0, m1);
                a[pp][0] = ffma2(m0, e00, a[pp][0]);
                a[pp][0] = ffma2(m1, e01, a[pp][0]);
                a[pp][1] = ffma2(m0, e10, a[pp][1]);
                a[pp][1] = ffma2(m1, e11, a[pp][1]);
            }
        }
#pragma unroll
        for (int j = 0; j < 2; j++) {
            int n = nh + 32 * j;
            if (n < nv) {
#pragma unroll
                for (int pp = 0; pp < 4; pp++) {
                    int p = 4 * pq + pp;
                    float sd = hadd2(a[pp][j]);
                    float x = sd * inv_se;
                    x = fminf(fmaxf(x, -30.f), 30.f);
                    float ex = __expf(-2.f * x);
                    float th = __fdividef(1.f - ex, 1.f + ex);
                    float lg = 10.f * th + Mb[(size_t)p * NN + base + n];
                    float w = __expf(lg - 10.f);
                    rs[pp] += w;
                    pout[(size_t)p * NN + base + n] = w;
                }
            }
        }
        __syncthreads();
    }

#pragma unroll
    for (int off = 16; off; off >>= 1) {
#pragma unroll
        for (int pp = 0; pp < 4; pp++)
            rs[pp] += __shfl_xor_sync(0xFFFFFFFFu, rs[pp], off);
    }
    if (nh == 0) {
#pragma unroll
        for (int pp = 0; pp < 4; pp++) inv_s[4 * pq + pp] = 1.f / rs[pp];
    }
    __syncthreads();
#pragma unroll
    for (int p = 0; p < 32; p++) {
        float ivp = inv_s[p];
        for (int i = t; i < NN; i += 256)
            pout[(size_t)p * NN + i] *= ivp;
    }
}

// ---------------------------------------------------------------------------
extern "C" void kernel_launch(void* const* d_in, const int* in_sizes, int n_in,
                              void* d_out, int out_size) {
    const float* enc  = (const float*)d_in[0];
    const float* last = (const float*)d_in[1];
    const float* attr = (const float*)d_in[2];
    const float* mask = (const float*)d_in[3];
    const float* Wq   = (const float*)d_in[4];
    const float* Wk   = (const float*)d_in[5];
    const float* Wv   = (const float*)d_in[6];
    const float* Wo   = (const float*)d_in[7];
    const float* bo   = (const float*)d_in[8];
    float* out = (float*)d_out;

    cudaFuncSetAttribute(attnA_kernel,
                         cudaFuncAttributeMaxDynamicSharedMemorySize, 73984);
    cudaFuncSetAttribute(phaseB_kernel,
                         cudaFuncAttributeMaxDynamicSharedMemorySize, 50816);

    proj_kernel<<<3024, 256>>>(enc, Wk, Wv, last, attr, Wq);
    attnA_kernel<<<512, 256, 73984>>>(mask);
    mh_proj<<<512, 256>>>(Wo, bo);
    phaseB_kernel<<<512, 256, 50816>>>(enc, mask, out);
}

// round 12
// speedup vs baseline: 1.3308x; 1.0966x over previous
#include <cuda_runtime.h>
#include <cstdint>

#define BB 64
#define PP 256
#define NN 1000
typedef unsigned long long ull;

__device__ float g_K[BB * NN * 128];
__device__ float g_V[BB * NN * 128];
__device__ float g_Q[BB * PP * 128];   // after attnA: holds attention output
#define g_MH g_K                       // mh reuses g_K (dead after attnA)

// ---- f32x2 / memory helpers ----
__device__ __forceinline__ ull ffma2(ull a, ull b, ull c) {
    ull d; asm("fma.rn.f32x2 %0,%1,%2,%3;" : "=l"(d) : "l"(a), "l"(b), "l"(c)); return d;
}
__device__ __forceinline__ ull fmul2(ull a, ull b) {
    ull d; asm("mul.rn.f32x2 %0,%1,%2;" : "=l"(d) : "l"(a), "l"(b)); return d;
}
__device__ __forceinline__ ull pack2(float lo, float hi) {
    ull d; asm("mov.b64 %0,{%1,%2};" : "=l"(d) : "f"(lo), "f"(hi)); return d;
}
__device__ __forceinline__ float hadd2(ull a) {
    float lo, hi; asm("mov.b64 {%0,%1},%2;" : "=f"(lo), "=f"(hi) : "l"(a)); return lo + hi;
}
__device__ __forceinline__ void lds2x64(const float* p, ull& a, ull& b) {
    uint32_t ad = (uint32_t)__cvta_generic_to_shared(p);
    asm("ld.shared.v2.b64 {%0,%1},[%2];" : "=l"(a), "=l"(b) : "r"(ad));
}
__device__ __forceinline__ ull lds64(const float* p) {
    uint32_t ad = (uint32_t)__cvta_generic_to_shared(p);
    ull a; asm("ld.shared.b64 %0,[%1];" : "=l"(a) : "r"(ad)); return a;
}
__device__ __forceinline__ void sts128z(float* p) {
    uint32_t ad = (uint32_t)__cvta_generic_to_shared(p);
    asm volatile("st.shared.v4.b32 [%0],{%1,%1,%1,%1};" :: "r"(ad), "r"(0));
}
__device__ __forceinline__ void sts128v(float* p, float v) {
    uint32_t ad = (uint32_t)__cvta_generic_to_shared(p);
    asm volatile("st.shared.v4.b32 [%0],{%1,%1,%1,%1};" :: "r"(ad), "f"(v));
}
__device__ __forceinline__ void ldg2x64(const float* p, ull& a, ull& b) {
    asm("ld.global.nc.v2.b64 {%0,%1},[%2];" : "=l"(a), "=l"(b) : "l"(p));
}
__device__ __forceinline__ void stg64(float* p, ull v) {
    asm volatile("st.global.b64 [%0],%1;" :: "l"(p), "l"(v));
}
__device__ __forceinline__ void cp16(float* dst, const float* src) {
    uint32_t d = (uint32_t)__cvta_generic_to_shared(dst);
    asm volatile("cp.async.cg.shared.global [%0],[%1],16;" :: "r"(d), "l"(src));
}
__device__ __forceinline__ void cp_commit() { asm volatile("cp.async.commit_group;"); }
template <int N> __device__ __forceinline__ void cp_wait() {
    asm volatile("cp.async.wait_group %0;" :: "n"(N));
}

// ---------------------------------------------------------------------------
// Kernel 1: fused K/V + Q projection (unchanged, ~124us).
// ---------------------------------------------------------------------------
__global__ __launch_bounds__(256) void proj_kernel(
        const float* __restrict__ enc, const float* __restrict__ Wk,
        const float* __restrict__ Wv, const float* __restrict__ last,
        const float* __restrict__ attr, const float* __restrict__ Wq) {
    __shared__ float xs[32 * 128];
    int t = threadIdx.x;

    if (blockIdx.x < 2000) {
        int row0 = blockIdx.x * 32;
        const float4* src = (const float4*)(enc + (size_t)row0 * 128);
        float4* xs4 = (float4*)xs;
#pragma unroll
        for (int i = t; i < 1024; i += 256) xs4[i] = src[i];
        __syncthreads();

        int mat = t >> 7, rh = (t >> 6) & 1, cp = t & 63;
        const float* W = mat ? Wv : Wk;
        float* out = mat ? g_V : g_K;
        const float* xb = xs + rh * 2048;

        ull acc[32];
#pragma unroll
        for (int i = 0; i < 32; i++) acc[i] = 0ull;

#pragma unroll 2
        for (int k = 0; k < 128; k += 2) {
            ull w0 = pack2(W[k * 128 + cp], W[(k + 1) * 128 + cp]);
            ull w1 = pack2(W[k * 128 + cp + 64], W[(k + 1) * 128 + cp + 64]);
#pragma unroll
            for (int r = 0; r < 16; r++) {
                ull x = lds64(xb + r * 128 + k);
                acc[r]      = ffma2(x, w0, acc[r]);
                acc[16 + r] = ffma2(x, w1, acc[16 + r]);
            }
        }
#pragma unroll
        for (int r = 0; r < 16; r++) {
            size_t row = (size_t)(row0 + rh * 16 + r) * 128;
            out[row + cp]      = hadd2(acc[r]);
            out[row + cp + 64] = hadd2(acc[16 + r]);
        }
    } else {
        int row0 = (blockIdx.x - 2000) * 16;
#pragma unroll
        for (int i = t; i < 2048; i += 256) {
            int r = i >> 7, c = i & 127;
            xs[r * 132 + c] = last[(size_t)(row0 + r) * 128 + c];
        }
        if (t < 16) xs[t * 132 + 128] = attr[row0 + t];
        __syncthreads();

        int rh = t >> 7, col = t & 127;
        const float* xr = xs + rh * 8 * 132;
        float acc[8] = {0, 0, 0, 0, 0, 0, 0, 0};
#pragma unroll 4
        for (int in = 0; in < 129; in++) {
            float w = Wq[in * 128 + col];
#pragma unroll
            for (int r = 0; r < 8; r++) acc[r] += xr[r * 132 + in] * w;
        }
#pragma unroll
        for (int r = 0; r < 8; r++)
            g_Q[(size_t)(row0 + rh * 8 + r) * 128 + col] = acc[r];
    }
}

// ---------------------------------------------------------------------------
// Kernel 2: flash attention.  32-query tiles, 512 blocks, 3 CTAs/SM.
// Mask staged via cp16 (stride 36). Output written in place over g_Q.
// smem: k0/k1 4096 | v0/v1 4096 | m0/m1 1152  = 18688 floats (74752 B)
// ---------------------------------------------------------------------------
__global__ __launch_bounds__(256, 3) void attnA_kernel(
        const float* __restrict__ mask) {
    extern __shared__ float work[];
    int t = threadIdx.x;
    int b = blockIdx.x >> 3;
    int p0 = (blockIdx.x & 7) * 32;
    int h = t >> 5, lane = t & 31;

    const float* Kb = g_K + (size_t)b * NN * 128;
    const float* Vb = g_V + (size_t)b * NN * 128;
    const float* Mb = mask + (size_t)(b * PP + p0) * NN;

    auto stageA = [&](int chunk) {
        int buf = chunk & 1;
        int base = chunk * 32;
        int nv = NN - base; if (nv > 32) nv = 32;
        float* kd = work + buf * 4096;
        float* vd = work + 8192 + buf * 4096;
        float* md = work + 16384 + buf * 1152;
#pragma unroll
        for (int j = 0; j < 4; j++) {
            int i = t + j * 256;
            int n = i >> 5, seg = i & 31;
            if (n < nv) {
                cp16(kd + n * 128 + seg * 4, Kb + (size_t)(base + n) * 128 + seg * 4);
                cp16(vd + n * 128 + seg * 4, Vb + (size_t)(base + n) * 128 + seg * 4);
            } else {
                sts128z(kd + n * 128 + seg * 4);
                sts128z(vd + n * 128 + seg * 4);
            }
        }
        {
            int p = t >> 3, seg = t & 7;   // 32 rows x 8 segs of 4
            if (seg * 4 < nv)
                cp16(md + p * 36 + seg * 4, Mb + (size_t)p * NN + base + seg * 4);
            else
                sts128v(md + p * 36 + seg * 4, -1e30f);
        }
    };

    // q (0.25 prescaled); read precedes in-place write
    ull qpk[8];
    {
        const float* qp = g_Q + (size_t)(b * PP + p0 + lane) * 128 + h * 16;
        ull c = pack2(0.25f, 0.25f);
#pragma unroll
        for (int j = 0; j < 4; j++) {
            ull a0, a1;
            ldg2x64(qp + 4 * j, a0, a1);
            qpk[2 * j]     = fmul2(a0, c);
            qpk[2 * j + 1] = fmul2(a1, c);
        }
    }

    float l = 0.f;
    ull acc[8];
#pragma unroll
    for (int j = 0; j < 8; j++) acc[j] = 0ull;

    stageA(0); cp_commit();
    stageA(1); cp_commit();

    for (int c = 0; c < 32; c++) {
        if (c == 31) cp_wait<0>(); else cp_wait<1>();
        __syncthreads();

        int buf = c & 1;
        const float* k_s = work + buf * 4096;
        const float* v_s = work + 8192 + buf * 4096;
        const float* mA  = work + 16384 + buf * 1152 + lane * 36;

#pragma unroll 4
        for (int n = 0; n < 32; n++) {
            const float* kp = k_s + n * 128 + h * 16;
            ull k0, k1, k2, k3, k4, k5, k6, k7;
            lds2x64(kp,      k0, k1);
            lds2x64(kp + 4,  k2, k3);
            lds2x64(kp + 8,  k4, k5);
            lds2x64(kp + 12, k6, k7);
            ull d = fmul2(qpk[0], k0);
            d = ffma2(qpk[1], k1, d); d = ffma2(qpk[2], k2, d);
            d = ffma2(qpk[3], k3, d); d = ffma2(qpk[4], k4, d);
            d = ffma2(qpk[5], k5, d); d = ffma2(qpk[6], k6, d);
            d = ffma2(qpk[7], k7, d);
            float w = __expf(hadd2(d) + mA[n]);
            l += w;
            const float* vp = v_s + n * 128 + h * 16;
            ull v0, v1, v2, v3, v4, v5, v6, v7;
            lds2x64(vp,      v0, v1);
            lds2x64(vp + 4,  v2, v3);
            lds2x64(vp + 8,  v4, v5);
            lds2x64(vp + 12, v6, v7);
            ull ww = pack2(w, w);
            acc[0] = ffma2(ww, v0, acc[0]); acc[1] = ffma2(ww, v1, acc[1]);
            acc[2] = ffma2(ww, v2, acc[2]); acc[3] = ffma2(ww, v3, acc[3]);
            acc[4] = ffma2(ww, v4, acc[4]); acc[5] = ffma2(ww, v5, acc[5]);
            acc[6] = ffma2(ww, v6, acc[6]); acc[7] = ffma2(ww, v7, acc[7]);
        }
        __syncthreads();
        if (c + 2 < 32) { stageA(c + 2); cp_commit(); }
    }

    {
        float inv = 1.f / l;
        ull iv = pack2(inv, inv);
        float* op = g_Q + (size_t)(b * PP + p0 + lane) * 128 + h * 16;
#pragma unroll
        for (int j = 0; j < 8; j++) stg64(op + 2 * j, fmul2(acc[j], iv));
    }
}

// ---------------------------------------------------------------------------
// Kernel 3: mh = out @ Wo + bo  (unchanged, ~20us).
// ---------------------------------------------------------------------------
__global__ __launch_bounds__(256) void mh_proj(const float* __restrict__ Wo,
                                               const float* __restrict__ bo) {
    __shared__ float xs[32 * 128];
    int t = threadIdx.x;
    int row0 = blockIdx.x * 32;
    const float4* src = (const float4*)(g_Q + (size_t)row0 * 128);
    float4* xs4 = (float4*)xs;
#pragma unroll
    for (int i = t; i < 1024; i += 256) xs4[i] = src[i];
    __syncthreads();

    int rg = t >> 6, cp = t & 63;
    const float* xb = xs + rg * 8 * 128;

    ull acc[16];
#pragma unroll
    for (int i = 0; i < 16; i++) acc[i] = 0ull;

#pragma unroll 2
    for (int k = 0; k < 128; k += 2) {
        ull w0 = pack2(Wo[k * 128 + cp], Wo[(k + 1) * 128 + cp]);
        ull w1 = pack2(Wo[k * 128 + cp + 64], Wo[(k + 1) * 128 + cp + 64]);
#pragma unroll
        for (int r = 0; r < 8; r++) {
            ull x = lds64(xb + r * 128 + k);
            acc[r]     = ffma2(x, w0, acc[r]);
            acc[8 + r] = ffma2(x, w1, acc[8 + r]);
        }
    }
    float b0 = bo[cp], b1 = bo[cp + 64];
#pragma unroll
    for (int r = 0; r < 8; r++) {
        size_t row = (size_t)(row0 + rg * 8 + r) * 128;
        g_MH[row + cp]      = hadd2(acc[r]) + b0;
        g_MH[row + cp + 64] = hadd2(acc[8 + r]) + b1;
    }
}

// ---------------------------------------------------------------------------
// Kernel 4: scoring, loop-inverted. block = (b, 64-node slice), 1024 blocks.
// enc slice staged ONCE; loop over 8 mh p-tiles of 32.
// Writes UNNORMALIZED weights to probs. 4 CTAs/SM.
// smem: enc 8448 | mh 4224 = 12672 floats (50688 B)
// ---------------------------------------------------------------------------
__global__ __launch_bounds__(256, 4) void phaseB_kernel(
        const float* __restrict__ enc, const float* __restrict__ mask,
        float* __restrict__ probs) {
    extern __shared__ float sm[];
    float* enc_s = sm;
    float* mh_s  = sm + 8448;

    int t = threadIdx.x;
    int b = blockIdx.x >> 4;
    int s = blockIdx.x & 15;
    int base = s * 64;
    int nv = NN - base; if (nv > 64) nv = 64;
    int pq = t >> 5, nh = t & 31;

    const float* Eb = enc + (size_t)b * NN * 128;
    const float* Mb = mask + (size_t)b * PP * NN;
    float* pout = probs + (size_t)b * PP * NN;
    const float inv_se = 0.08838834764831845f;

    // stage enc slice (once)
#pragma unroll
    for (int j = 0; j < 8; j++) {
        int i = t + j * 256;
        int n = i >> 5, seg = i & 31;
        if (n < nv)
            cp16(enc_s + n * 132 + seg * 4, Eb + (size_t)(base + n) * 128 + seg * 4);
    }
    cp_commit();

    const float* e0p = enc_s + nh * 132;
    const float* e1p = enc_s + (nh + 32) * 132;

    for (int pt = 0; pt < 8; pt++) {
        __syncthreads();    // previous tile's mh_s reads done
        // stage mh tile
#pragma unroll
        for (int j = 0; j < 4; j++) {
            int i = t + j * 256;
            int row = i >> 5, seg = i & 31;
            cp16(mh_s + row * 132 + seg * 4,
                 g_MH + (size_t)(b * PP + pt * 32 + row) * 128 + seg * 4);
        }
        cp_commit(); cp_wait<0>();
        __syncthreads();

        const float* mrow = mh_s + (4 * pq) * 132;
        ull a[4][2];
#pragma unroll
        for (int pp = 0; pp < 4; pp++) { a[pp][0] = 0ull; a[pp][1] = 0ull; }

#pragma unroll 4
        for (int k = 0; k < 128; k += 4) {
            ull e00, e01, e10, e11;
            lds2x64(e0p + k, e00, e01);
            lds2x64(e1p + k, e10, e11);
#pragma unroll
            for (int pp = 0; pp < 4; pp++) {
                ull m0, m1;
                lds2x64(mrow + pp * 132 + k, m0, m1);
                a[pp][0] = ffma2(m0, e00, a[pp][0]);
                a[pp][0] = ffma2(m1, e01, a[pp][0]);
                a[pp][1] = ffma2(m0, e10, a[pp][1]);
                a[pp][1] = ffma2(m1, e11, a[pp][1]);
            }
        }
#pragma unroll
        for (int j = 0; j < 2; j++) {
            int n = nh + 32 * j;
            if (n < nv) {
#pragma unroll
                for (int pp = 0; pp < 4; pp++) {
                    int p = pt * 32 + 4 * pq + pp;
                    float sd = hadd2(a[pp][j]);
                    float x = sd * inv_se;
                    x = fminf(fmaxf(x, -30.f), 30.f);
                    float ex = __expf(-2.f * x);
                    float th = __fdividef(1.f - ex, 1.f + ex);
                    float lg = 10.f * th + Mb[(size_t)p * NN + base + n];
                    pout[(size_t)p * NN + base + n] = __expf(lg - 10.f);
                }
            }
        }
    }
}

// ---------------------------------------------------------------------------
// Kernel 5: row-sum + rescale. 512 blocks x 32 rows; warp = 4 rows.
// ---------------------------------------------------------------------------
__global__ __launch_bounds__(256) void norm_kernel(float* __restrict__ probs) {
    int t = threadIdx.x;
    int row0 = blockIdx.x * 32 + (t >> 5) * 4;
    int lane = t & 31;
#pragma unroll
    for (int r = 0; r < 4; r++) {
        float* pr = probs + (size_t)(row0 + r) * NN;
        float sum = 0.f;
        for (int i = lane; i < NN; i += 32) sum += pr[i];
#pragma unroll
        for (int off = 16; off; off >>= 1)
            sum += __shfl_xor_sync(0xFFFFFFFFu, sum, off);
        float inv = 1.f / sum;
        for (int i = lane; i < NN; i += 32) pr[i] *= inv;
    }
}

// ---------------------------------------------------------------------------
extern "C" void kernel_launch(void* const* d_in, const int* in_sizes, int n_in,
                              void* d_out, int out_size) {
    const float* enc  = (const float*)d_in[0];
    const float* last = (const float*)d_in[1];
    const float* attr = (const float*)d_in[2];
    const float* mask = (const float*)d_in[3];
    const float* Wq   = (const float*)d_in[4];
    const float* Wk   = (const float*)d_in[5];
    const float* Wv   = (const float*)d_in[6];
    const float* Wo   = (const float*)d_in[7];
    const float* bo   = (const float*)d_in[8];
    float* out = (float*)d_out;

    cudaFuncSetAttribute(attnA_kernel,
                         cudaFuncAttributeMaxDynamicSharedMemorySize, 74752);
    cudaFuncSetAttribute(phaseB_kernel,
                         cudaFuncAttributeMaxDynamicSharedMemorySize, 50688);

    proj_kernel<<<3024, 256>>>(enc, Wk, Wv, last, attr, Wq);
    attnA_kernel<<<512, 256, 74752>>>(mask);
    mh_proj<<<512, 256>>>(Wo, bo);
    phaseB_kernel<<<1024, 256, 50688>>>(enc, mask, out);
    norm_kernel<<<512, 256>>>(out);
}

// round 13
// speedup vs baseline: 1.5066x; 1.1321x over previous
#include <cuda_runtime.h>
#include <cstdint>

#define BB 64
#define PP 256
#define NN 1000
typedef unsigned long long ull;

__device__ float g_K[BB * NN * 128];
__device__ float g_V[BB * NN * 128];
__device__ float g_Q[BB * PP * 128];   // after attnA: holds attention output
#define g_MH g_K                       // mh reuses g_K (dead after attnA)

// ---- f32x2 / memory helpers ----
__device__ __forceinline__ ull ffma2(ull a, ull b, ull c) {
    ull d; asm("fma.rn.f32x2 %0,%1,%2,%3;" : "=l"(d) : "l"(a), "l"(b), "l"(c)); return d;
}
__device__ __forceinline__ ull fmul2(ull a, ull b) {
    ull d; asm("mul.rn.f32x2 %0,%1,%2;" : "=l"(d) : "l"(a), "l"(b)); return d;
}
__device__ __forceinline__ ull pack2(float lo, float hi) {
    ull d; asm("mov.b64 %0,{%1,%2};" : "=l"(d) : "f"(lo), "f"(hi)); return d;
}
__device__ __forceinline__ float hadd2(ull a) {
    float lo, hi; asm("mov.b64 {%0,%1},%2;" : "=f"(lo), "=f"(hi) : "l"(a)); return lo + hi;
}
__device__ __forceinline__ void lds2x64(const float* p, ull& a, ull& b) {
    uint32_t ad = (uint32_t)__cvta_generic_to_shared(p);
    asm("ld.shared.v2.b64 {%0,%1},[%2];" : "=l"(a), "=l"(b) : "r"(ad));
}
__device__ __forceinline__ ull lds64(const float* p) {
    uint32_t ad = (uint32_t)__cvta_generic_to_shared(p);
    ull a; asm("ld.shared.b64 %0,[%1];" : "=l"(a) : "r"(ad)); return a;
}
__device__ __forceinline__ void sts128z(float* p) {
    uint32_t ad = (uint32_t)__cvta_generic_to_shared(p);
    asm volatile("st.shared.v4.b32 [%0],{%1,%1,%1,%1};" :: "r"(ad), "r"(0));
}
__device__ __forceinline__ void sts128v(float* p, float v) {
    uint32_t ad = (uint32_t)__cvta_generic_to_shared(p);
    asm volatile("st.shared.v4.b32 [%0],{%1,%1,%1,%1};" :: "r"(ad), "f"(v));
}
__device__ __forceinline__ void ldg2x64(const float* p, ull& a, ull& b) {
    asm("ld.global.nc.v2.b64 {%0,%1},[%2];" : "=l"(a), "=l"(b) : "l"(p));
}
__device__ __forceinline__ void stg64(float* p, ull v) {
    asm volatile("st.global.b64 [%0],%1;" :: "l"(p), "l"(v));
}
__device__ __forceinline__ void cp16(float* dst, const float* src) {
    uint32_t d = (uint32_t)__cvta_generic_to_shared(dst);
    asm volatile("cp.async.cg.shared.global [%0],[%1],16;" :: "r"(d), "l"(src));
}
__device__ __forceinline__ void cp_commit() { asm volatile("cp.async.commit_group;"); }
template <int N> __device__ __forceinline__ void cp_wait() {
    asm volatile("cp.async.wait_group %0;" :: "n"(N));
}

// ---------------------------------------------------------------------------
// Kernel 1: fused K/V + Q projection (unchanged, ~124us).
// ---------------------------------------------------------------------------
__global__ __launch_bounds__(256) void proj_kernel(
        const float* __restrict__ enc, const float* __restrict__ Wk,
        const float* __restrict__ Wv, const float* __restrict__ last,
        const float* __restrict__ attr, const float* __restrict__ Wq) {
    __shared__ float xs[32 * 128];
    int t = threadIdx.x;

    if (blockIdx.x < 2000) {
        int row0 = blockIdx.x * 32;
        const float4* src = (const float4*)(enc + (size_t)row0 * 128);
        float4* xs4 = (float4*)xs;
#pragma unroll
        for (int i = t; i < 1024; i += 256) xs4[i] = src[i];
        __syncthreads();

        int mat = t >> 7, rh = (t >> 6) & 1, cp = t & 63;
        const float* W = mat ? Wv : Wk;
        float* out = mat ? g_V : g_K;
        const float* xb = xs + rh * 2048;

        ull acc[32];
#pragma unroll
        for (int i = 0; i < 32; i++) acc[i] = 0ull;

#pragma unroll 2
        for (int k = 0; k < 128; k += 2) {
            ull w0 = pack2(W[k * 128 + cp], W[(k + 1) * 128 + cp]);
            ull w1 = pack2(W[k * 128 + cp + 64], W[(k + 1) * 128 + cp + 64]);
#pragma unroll
            for (int r = 0; r < 16; r++) {
                ull x = lds64(xb + r * 128 + k);
                acc[r]      = ffma2(x, w0, acc[r]);
                acc[16 + r] = ffma2(x, w1, acc[16 + r]);
            }
        }
#pragma unroll
        for (int r = 0; r < 16; r++) {
            size_t row = (size_t)(row0 + rh * 16 + r) * 128;
            out[row + cp]      = hadd2(acc[r]);
            out[row + cp + 64] = hadd2(acc[16 + r]);
        }
    } else {
        int row0 = (blockIdx.x - 2000) * 16;
#pragma unroll
        for (int i = t; i < 2048; i += 256) {
            int r = i >> 7, c = i & 127;
            xs[r * 132 + c] = last[(size_t)(row0 + r) * 128 + c];
        }
        if (t < 16) xs[t * 132 + 128] = attr[row0 + t];
        __syncthreads();

        int rh = t >> 7, col = t & 127;
        const float* xr = xs + rh * 8 * 132;
        float acc[8] = {0, 0, 0, 0, 0, 0, 0, 0};
#pragma unroll 4
        for (int in = 0; in < 129; in++) {
            float w = Wq[in * 128 + col];
#pragma unroll
            for (int r = 0; r < 8; r++) acc[r] += xr[r * 132 + in] * w;
        }
#pragma unroll
        for (int r = 0; r < 8; r++)
            g_Q[(size_t)(row0 + rh * 8 + r) * 128 + col] = acc[r];
    }
}

// ---------------------------------------------------------------------------
// Kernel 2: flash attention, 2 queries per lane. 64-q tiles, 256 blocks.
// warp = head h; lane owns queries (lane, lane+32). Each K/V broadcast
// feeds 2 queries -> LDS floor halves.
// smem floats: k0/k1 4096 ea | v0/v1 4096 ea | m0/m1 2304 ea = 20992 (83968 B)
// ---------------------------------------------------------------------------
__global__ __launch_bounds__(256) void attnA_kernel(
        const float* __restrict__ mask) {
    extern __shared__ float work[];
    int t = threadIdx.x;
    int b = blockIdx.x >> 2;
    int p0 = (blockIdx.x & 3) * 64;
    int h = t >> 5, lane = t & 31;

    const float* Kb = g_K + (size_t)b * NN * 128;
    const float* Vb = g_V + (size_t)b * NN * 128;
    const float* Mb = mask + (size_t)(b * PP + p0) * NN;

    auto stageA = [&](int chunk) {
        int buf = chunk & 1;
        int base = chunk * 32;
        int nv = NN - base; if (nv > 32) nv = 32;
        float* kd = work + buf * 4096;
        float* vd = work + 8192 + buf * 4096;
        float* md = work + 16384 + buf * 2304;
#pragma unroll
        for (int j = 0; j < 4; j++) {
            int i = t + j * 256;
            int n = i >> 5, seg = i & 31;
            if (n < nv) {
                cp16(kd + n * 128 + seg * 4, Kb + (size_t)(base + n) * 128 + seg * 4);
                cp16(vd + n * 128 + seg * 4, Vb + (size_t)(base + n) * 128 + seg * 4);
            } else {
                sts128z(kd + n * 128 + seg * 4);
                sts128z(vd + n * 128 + seg * 4);
            }
        }
        // mask: 64 rows x 8 segs of 4
#pragma unroll
        for (int j = 0; j < 2; j++) {
            int i = t + j * 256;
            int p = i >> 3, seg = i & 7;
            if (seg * 4 < nv)
                cp16(md + p * 36 + seg * 4, Mb + (size_t)p * NN + base + seg * 4);
            else
                sts128v(md + p * 36 + seg * 4, -1e30f);
        }
    };

    // q for both queries (0.25 prescaled); reads precede in-place writes
    ull qA[8], qB[8];
    {
        const float* qp = g_Q + (size_t)(b * PP + p0 + lane) * 128 + h * 16;
        const float* qp2 = qp + 32 * 128;
        ull c = pack2(0.25f, 0.25f);
#pragma unroll
        for (int j = 0; j < 4; j++) {
            ull a0, a1;
            ldg2x64(qp + 4 * j, a0, a1);
            qA[2 * j]     = fmul2(a0, c);
            qA[2 * j + 1] = fmul2(a1, c);
            ull b0, b1;
            ldg2x64(qp2 + 4 * j, b0, b1);
            qB[2 * j]     = fmul2(b0, c);
            qB[2 * j + 1] = fmul2(b1, c);
        }
    }

    float lA = 0.f, lB = 0.f;
    ull accA[8], accB[8];
#pragma unroll
    for (int j = 0; j < 8; j++) { accA[j] = 0ull; accB[j] = 0ull; }

    stageA(0); cp_commit();
    stageA(1); cp_commit();

    for (int c = 0; c < 32; c++) {
        if (c == 31) cp_wait<0>(); else cp_wait<1>();
        __syncthreads();

        int buf = c & 1;
        const float* k_s = work + buf * 4096;
        const float* v_s = work + 8192 + buf * 4096;
        const float* md  = work + 16384 + buf * 2304;
        const float* mA = md + lane * 36;
        const float* mB = md + (lane + 32) * 36;

#pragma unroll 2
        for (int n = 0; n < 32; n++) {
            const float* kp = k_s + n * 128 + h * 16;
            ull k0, k1, k2, k3, k4, k5, k6, k7;
            lds2x64(kp,      k0, k1);
            lds2x64(kp + 4,  k2, k3);
            lds2x64(kp + 8,  k4, k5);
            lds2x64(kp + 12, k6, k7);
            ull dA = fmul2(qA[0], k0);
            ull dB = fmul2(qB[0], k0);
            dA = ffma2(qA[1], k1, dA); dB = ffma2(qB[1], k1, dB);
            dA = ffma2(qA[2], k2, dA); dB = ffma2(qB[2], k2, dB);
            dA = ffma2(qA[3], k3, dA); dB = ffma2(qB[3], k3, dB);
            dA = ffma2(qA[4], k4, dA); dB = ffma2(qB[4], k4, dB);
            dA = ffma2(qA[5], k5, dA); dB = ffma2(qB[5], k5, dB);
            dA = ffma2(qA[6], k6, dA); dB = ffma2(qB[6], k6, dB);
            dA = ffma2(qA[7], k7, dA); dB = ffma2(qB[7], k7, dB);
            float wA = __expf(hadd2(dA) + mA[n]);
            float wB = __expf(hadd2(dB) + mB[n]);
            lA += wA; lB += wB;
            const float* vp = v_s + n * 128 + h * 16;
            ull v0, v1, v2, v3, v4, v5, v6, v7;
            lds2x64(vp,      v0, v1);
            lds2x64(vp + 4,  v2, v3);
            lds2x64(vp + 8,  v4, v5);
            lds2x64(vp + 12, v6, v7);
            ull wwA = pack2(wA, wA);
            ull wwB = pack2(wB, wB);
            accA[0] = ffma2(wwA, v0, accA[0]); accB[0] = ffma2(wwB, v0, accB[0]);
            accA[1] = ffma2(wwA, v1, accA[1]); accB[1] = ffma2(wwB, v1, accB[1]);
            accA[2] = ffma2(wwA, v2, accA[2]); accB[2] = ffma2(wwB, v2, accB[2]);
            accA[3] = ffma2(wwA, v3, accA[3]); accB[3] = ffma2(wwB, v3, accB[3]);
            accA[4] = ffma2(wwA, v4, accA[4]); accB[4] = ffma2(wwB, v4, accB[4]);
            accA[5] = ffma2(wwA, v5, accA[5]); accB[5] = ffma2(wwB, v5, accB[5]);
            accA[6] = ffma2(wwA, v6, accA[6]); accB[6] = ffma2(wwB, v6, accB[6]);
            accA[7] = ffma2(wwA, v7, accA[7]); accB[7] = ffma2(wwB, v7, accB[7]);
        }
        __syncthreads();
        if (c + 2 < 32) { stageA(c + 2); cp_commit(); }
    }

    {
        float ivA = 1.f / lA, ivB = 1.f / lB;
        ull iA = pack2(ivA, ivA), iB = pack2(ivB, ivB);
        float* opA = g_Q + (size_t)(b * PP + p0 + lane) * 128 + h * 16;
        float* opB = opA + 32 * 128;
#pragma unroll
        for (int j = 0; j < 8; j++) {
            stg64(opA + 2 * j, fmul2(accA[j], iA));
            stg64(opB + 2 * j, fmul2(accB[j], iB));
        }
    }
}

// ---------------------------------------------------------------------------
// Kernel 3: mh = out @ Wo + bo  (unchanged, ~20us).
// ---------------------------------------------------------------------------
__global__ __launch_bounds__(256) void mh_proj(const float* __restrict__ Wo,
                                               const float* __restrict__ bo) {
    __shared__ float xs[32 * 128];
    int t = threadIdx.x;
    int row0 = blockIdx.x * 32;
    const float4* src = (const float4*)(g_Q + (size_t)row0 * 128);
    float4* xs4 = (float4*)xs;
#pragma unroll
    for (int i = t; i < 1024; i += 256) xs4[i] = src[i];
    __syncthreads();

    int rg = t >> 6, cp = t & 63;
    const float* xb = xs + rg * 8 * 128;

    ull acc[16];
#pragma unroll
    for (int i = 0; i < 16; i++) acc[i] = 0ull;

#pragma unroll 2
    for (int k = 0; k < 128; k += 2) {
        ull w0 = pack2(Wo[k * 128 + cp], Wo[(k + 1) * 128 + cp]);
        ull w1 = pack2(Wo[k * 128 + cp + 64], Wo[(k + 1) * 128 + cp + 64]);
#pragma unroll
        for (int r = 0; r < 8; r++) {
            ull x = lds64(xb + r * 128 + k);
            acc[r]     = ffma2(x, w0, acc[r]);
            acc[8 + r] = ffma2(x, w1, acc[8 + r]);
        }
    }
    float b0 = bo[cp], b1 = bo[cp + 64];
#pragma unroll
    for (int r = 0; r < 8; r++) {
        size_t row = (size_t)(row0 + rg * 8 + r) * 128;
        g_MH[row + cp]      = hadd2(acc[r]) + b0;
        g_MH[row + cp + 64] = hadd2(acc[8 + r]) + b1;
    }
}

// ---------------------------------------------------------------------------
// Kernel 4: scoring, loop-inverted, 64-row mh tiles. block = (b, 64-node
// slice), 1024 blocks; thread = 8p x 2n; 4 tile iterations. 3 CTAs/SM.
// smem: enc 8448 | mh 8448 = 16896 floats (67584 B)
// ---------------------------------------------------------------------------
__global__ __launch_bounds__(256, 3) void phaseB_kernel(
        const float* __restrict__ enc, const float* __restrict__ mask,
        float* __restrict__ probs) {
    extern __shared__ float sm[];
    float* enc_s = sm;
    float* mh_s  = sm + 8448;

    int t = threadIdx.x;
    int b = blockIdx.x >> 4;
    int s = blockIdx.x & 15;
    int base = s * 64;
    int nv = NN - base; if (nv > 64) nv = 64;
    int pq = t >> 5, nh = t & 31;

    const float* Eb = enc + (size_t)b * NN * 128;
    const float* Mb = mask + (size_t)b * PP * NN;
    float* pout = probs + (size_t)b * PP * NN;
    const float inv_se = 0.08838834764831845f;

    // stage enc slice (once)
#pragma unroll
    for (int j = 0; j < 8; j++) {
        int i = t + j * 256;
        int n = i >> 5, seg = i & 31;
        if (n < nv)
            cp16(enc_s + n * 132 + seg * 4, Eb + (size_t)(base + n) * 128 + seg * 4);
    }
    cp_commit();

    const float* e0p = enc_s + nh * 132;
    const float* e1p = enc_s + (nh + 32) * 132;

    for (int pt = 0; pt < 4; pt++) {
        __syncthreads();    // previous tile's mh_s reads done
        // stage 64-row mh tile
#pragma unroll
        for (int j = 0; j < 8; j++) {
            int i = t + j * 256;
            int row = i >> 5, seg = i & 31;
            cp16(mh_s + row * 132 + seg * 4,
                 g_MH + (size_t)(b * PP + pt * 64 + row) * 128 + seg * 4);
        }
        cp_commit(); cp_wait<0>();
        __syncthreads();

        const float* mrow = mh_s + (8 * pq) * 132;
        ull a[8][2];
#pragma unroll
        for (int pp = 0; pp < 8; pp++) { a[pp][0] = 0ull; a[pp][1] = 0ull; }

#pragma unroll 2
        for (int k = 0; k < 128; k += 4) {
            ull e00, e01, e10, e11;
            lds2x64(e0p + k, e00, e01);
            lds2x64(e1p + k, e10, e11);
#pragma unroll
            for (int pp = 0; pp < 8; pp++) {
                ull m0, m1;
                lds2x64(mrow + pp * 132 + k, m0, m1);
                a[pp][0] = ffma2(m0, e00, a[pp][0]);
                a[pp][0] = ffma2(m1, e01, a[pp][0]);
                a[pp][1] = ffma2(m0, e10, a[pp][1]);
                a[pp][1] = ffma2(m1, e11, a[pp][1]);
            }
        }
#pragma unroll
        for (int j = 0; j < 2; j++) {
            int n = nh + 32 * j;
            if (n < nv) {
#pragma unroll
                for (int pp = 0; pp < 8; pp++) {
                    int p = pt * 64 + 8 * pq + pp;
                    float sd = hadd2(a[pp][j]);
                    float x = sd * inv_se;
                    x = fminf(fmaxf(x, -30.f), 30.f);
                    float ex = __expf(-2.f * x);
                    float th = __fdividef(1.f - ex, 1.f + ex);
                    float lg = 10.f * th + Mb[(size_t)p * NN + base + n];
                    pout[(size_t)p * NN + base + n] = __expf(lg - 10.f);
                }
            }
        }
    }
}

// ---------------------------------------------------------------------------
// Kernel 5: row-sum + rescale (unchanged).
// ---------------------------------------------------------------------------
__global__ __launch_bounds__(256) void norm_kernel(float* __restrict__ probs) {
    int t = threadIdx.x;
    int row0 = blockIdx.x * 32 + (t >> 5) * 4;
    int lane = t & 31;
#pragma unroll
    for (int r = 0; r < 4; r++) {
        float* pr = probs + (size_t)(row0 + r) * NN;
        float sum = 0.f;
        for (int i = lane; i < NN; i += 32) sum += pr[i];
#pragma unroll
        for (int off = 16; off; off >>= 1)
            sum += __shfl_xor_sync(0xFFFFFFFFu, sum, off);
        float inv = 1.f / sum;
        for (int i = lane; i < NN; i += 32) pr[i] *= inv;
    }
}

// ---------------------------------------------------------------------------
extern "C" void kernel_launch(void* const* d_in, const int* in_sizes, int n_in,
                              void* d_out, int out_size) {
    const float* enc  = (const float*)d_in[0];
    const float* last = (const float*)d_in[1];
    const float* attr = (const float*)d_in[2];
    const float* mask = (const float*)d_in[3];
    const float* Wq   = (const float*)d_in[4];
    const float* Wk   = (const float*)d_in[5];
    const float* Wv   = (const float*)d_in[6];
    const float* Wo   = (const float*)d_in[7];
    const float* bo   = (const float*)d_in[8];
    float* out = (float*)d_out;

    cudaFuncSetAttribute(attnA_kernel,
                         cudaFuncAttributeMaxDynamicSharedMemorySize, 83968);
    cudaFuncSetAttribute(phaseB_kernel,
                         cudaFuncAttributeMaxDynamicSharedMemorySize, 67584);

    proj_kernel<<<3024, 256>>>(enc, Wk, Wv, last, attr, Wq);
    attnA_kernel<<<256, 256, 83968>>>(mask);
    mh_proj<<<512, 256>>>(Wo, bo);
    phaseB_kernel<<<1024, 256, 67584>>>(enc, mask, out);
    norm_kernel<<<512, 256>>>(out);
}